// round 14
// baseline (speedup 1.0000x reference)
#include <cuda_runtime.h>
#include <math.h>
#include <stdint.h>

#define NN 2048
#define MM 2048
#define DD 1024
#define BAND 24
#define WB 49             // 2*BAND+1; f32 kappa support is |i-j| <~ 22
#define KCH 4
#define KLEN (DD / KCH)   // 256
#define NTILE (NN / 32)   // 64 GEMM row-tiles
#define NCL 8             // cluster CTAs
#define RPC 256           // rows per cluster CTA
#define EXT 304           // extended v/w rows per CTA [R0-24, R0+280)
#define WIN 352           // u window rows [R0-48, R0+304)
#define STPB 512          // sink threads per CTA (2 threads per row)
#define SKT_SZ (EXT * WB) // 14896 floats
#define SKB_SZ (RPC * WB) // 12544 floats
#define SMEM_DYN ((SKT_SZ + SKB_SZ) * 4)

#define LOG2E    1.4426950408889634074
#define K2       14.426950408889634074    // 10*log2(e)
#define L2ISQ2PI (-1.3257480647361593)    // log2(1/sqrt(2*pi))
#define INV_M    (1.0f / 2048.0f)

// ---------------- scratch ----------------
__device__ __align__(16) float  g_cx[DD], g_cy[DD];
__device__ __align__(16) float  g_Xn[NN * DD];
__device__ __align__(16) float  g_Yn[MM * DD];
__device__ __align__(16) float  g_xsq[NN], g_ysq[MM];
__device__ __align__(16) float  g_dpart[KCH * NN * WB];
__device__ __align__(16) float  g_dband[NN * WB];     // row-major d[i][c], j = i + c - BAND
__device__ __align__(16) float  g_kbC [WB * NN];      // kappa[i][c]  at [c*NN + i] (col-major)
__device__ __align__(16) float  g_kbTC[WB * NN];      // kappaT[j][c] at [c*NN + j] (col-major)
__device__ __align__(16) float  g_kbR [NN * WB];      // kappa row-major (finalize)
__device__ __align__(16) double g_lps[WB];
__device__ double g_la[NN];
__device__ float  g_u[NN], g_v[NN];
__device__ double g_part[NCL], g_part2[256];
__device__ int    g_tilecnt[NTILE];
__device__ int    g_fincnt;

#define CLUSTER_SYNC() do { \
    asm volatile("barrier.cluster.arrive.aligned;" ::: "memory"); \
    asm volatile("barrier.cluster.wait.aligned;"   ::: "memory"); } while (0)

__device__ __forceinline__ unsigned ctarank() {
    unsigned r; asm("mov.u32 %0, %%cluster_ctarank;" : "=r"(r)); return r;
}
__device__ __forceinline__ uint32_t smem_u32(const void* p) {
    uint32_t a;
    asm("{ .reg .u64 t; cvta.to.shared.u64 t, %1; cvt.u32.u64 %0, t; }" : "=r"(a) : "l"(p));
    return a;
}
#define MBAR_INIT(addr, cnt) \
    asm volatile("mbarrier.init.shared.b64 [%0], %1;" :: "r"(addr), "r"(cnt) : "memory")
// push one f32 into the same smem offset of CTA `rank`, then release-arrive on its barrier
#define PUSH_ARRIVE(slot_addr, mbar_addr, rank, val) \
    asm volatile("{ .reg .b32 ra, rb;\n\t" \
                 "mapa.shared::cluster.u32 ra, %0, %2;\n\t" \
                 "st.shared::cluster.f32 [ra], %3;\n\t" \
                 "mapa.shared::cluster.u32 rb, %1, %2;\n\t" \
                 "mbarrier.arrive.release.cluster.shared::cluster.b64 _, [rb];\n\t}" \
                 :: "r"(slot_addr), "r"(mbar_addr), "r"(rank), "f"(val) : "memory")
#define TRYWAIT_PAR(mbar_addr, par) do { \
    unsigned done_ = 0; \
    while (!done_) { \
        asm volatile("{ .reg .pred p;\n\t" \
                     "mbarrier.try_wait.parity.acquire.cluster.shared::cta.b64 p, [%1], %2, 0x989680;\n\t" \
                     "selp.b32 %0, 1, 0, p;\n\t}" \
                     : "=r"(done_) : "r"(mbar_addr), "r"((unsigned)(par)) : "memory"); \
    } } while (0)

// ---------------- L1: column stats (X and Y) + init  (32x16 threads) ----------------
__global__ void colstats_k(const float* __restrict__ X, const float* __restrict__ Y) {
    int lt = threadIdx.y * 32 + threadIdx.x;
    if (blockIdx.x == 0 && blockIdx.y == 0) {
        if (lt < NTILE) g_tilecnt[lt] = 0;
        if (lt == 0)    g_fincnt = 0;
        if (lt < WB) {
            double off = (double)(BAND - lt);
            double di  = off / (double)NN;
            double l2p = -(off * off * 0.25) * LOG2E + L2ISQ2PI;
            double s   = 50.0 / (di * di + 1.0);
            g_lps[lt] = l2p + s * K2;
        }
    }
    const float* A = blockIdx.y ? Y : X;
    int col = blockIdx.x * 32 + threadIdx.x;
    double s = 0.0, s2 = 0.0;
#pragma unroll 8
    for (int r = threadIdx.y; r < NN; r += 16) {
        double v = (double)A[r * DD + col];
        s += v; s2 += v * v;
    }
    __shared__ double shs[16][32], shs2[16][32];
    shs[threadIdx.y][threadIdx.x] = s;
    shs2[threadIdx.y][threadIdx.x] = s2;
    __syncthreads();
    if (threadIdx.y == 0) {
        for (int y = 1; y < 16; y++) { s += shs[y][threadIdx.x]; s2 += shs2[y][threadIdx.x]; }
        double mean = s / (double)NN;
        double var  = (s2 - (double)NN * mean * mean) / (double)(NN - 1);
        float  c    = (float)(mean / sqrt(var + 1e-4));
        (blockIdx.y ? g_cy : g_cx)[col] = c;
    }
}

// ---------------- L2: fused normalize + row squared norm ----------------
__global__ void normrow_k(const float* __restrict__ X, const float* __restrict__ Y) {
    int isY = blockIdx.y;
    const float* A = isY ? Y : X;
    const float* C = isY ? g_cy : g_cx;
    float* O       = isY ? g_Yn : g_Xn;
    int r = blockIdx.x, t = threadIdx.x;             // 256 threads
    float4 a = ((const float4*)(A + (size_t)r * DD))[t];
    float4 c = ((const float4*)C)[t];
    float4 o = make_float4(a.x - c.x, a.y - c.y, a.z - c.z, a.w - c.w);
    ((float4*)(O + (size_t)r * DD))[t] = o;
    double s = (double)o.x * o.x + (double)o.y * o.y + (double)o.z * o.z + (double)o.w * o.w;
    __shared__ double sh[256];
    sh[t] = s; __syncthreads();
    for (int off = 128; off > 0; off >>= 1) {
        if (t < off) sh[t] += sh[t + off];
        __syncthreads();
    }
    if (t == 0) (isY ? g_ysq : g_xsq)[r] = (float)sh[0];
}

// ---------------- L3: band GEMM (split-K x4) + fused d/la/kappa epilogue ----------------
__global__ void band_gemm_k() {
    int ti = blockIdx.x;
    int i0 = ti * 32;
    int j0 = i0 - 32;
    int cz = blockIdx.y;

    __shared__ float Xs[32][33];
    __shared__ float Ys[96][33];
    int tid = threadIdx.x;                           // 256 threads
    int tx = tid & 31, ty = tid >> 5;
    float acc[4][3];
#pragma unroll
    for (int a = 0; a < 4; a++)
#pragma unroll
        for (int bb = 0; bb < 3; bb++) acc[a][bb] = 0.f;

    for (int k0 = 0; k0 < KLEN; k0 += 32) {
        {
            int r = tid >> 3, q = tid & 7;
            float4 v = *(const float4*)(g_Xn + (size_t)(i0 + r) * DD + cz * KLEN + k0 + q * 4);
            Xs[r][q * 4 + 0] = v.x; Xs[r][q * 4 + 1] = v.y;
            Xs[r][q * 4 + 2] = v.z; Xs[r][q * 4 + 3] = v.w;
        }
#pragma unroll
        for (int l = 0; l < 3; l++) {
            int li = tid + l * 256;
            int r = li >> 3, q = li & 7;
            int gj = j0 + r;
            float4 v = make_float4(0.f, 0.f, 0.f, 0.f);
            if ((unsigned)gj < NN)
                v = *(const float4*)(g_Yn + (size_t)gj * DD + cz * KLEN + k0 + q * 4);
            Ys[r][q * 4 + 0] = v.x; Ys[r][q * 4 + 1] = v.y;
            Ys[r][q * 4 + 2] = v.z; Ys[r][q * 4 + 3] = v.w;
        }
        __syncthreads();
#pragma unroll
        for (int kk = 0; kk < 32; kk++) {
            float av[4], bv[3];
#pragma unroll
            for (int a = 0; a < 4; a++) av[a] = Xs[ty * 4 + a][kk];
#pragma unroll
            for (int bb = 0; bb < 3; bb++) bv[bb] = Ys[tx * 3 + bb][kk];
#pragma unroll
            for (int a = 0; a < 4; a++)
#pragma unroll
                for (int bb = 0; bb < 3; bb++) acc[a][bb] += av[a] * bv[bb];
        }
        __syncthreads();
    }

#pragma unroll
    for (int a = 0; a < 4; a++) {
        int gi = i0 + ty * 4 + a;
#pragma unroll
        for (int bb = 0; bb < 3; bb++) {
            int gj = j0 + tx * 3 + bb;
            int c = gj - gi + BAND;
            if ((unsigned)gj < NN && c >= 0 && c < WB)
                g_dpart[((size_t)cz * NN + gi) * WB + c] = acc[a][bb];
        }
    }

    // split-K fixup: last arriver runs the epilogue (deterministic math)
    __shared__ int s_old;
    __shared__ double sla[32];
    __threadfence();
    __syncthreads();
    if (tid == 0) s_old = atomicAdd(&g_tilecnt[ti], 1);
    __syncthreads();
    if (s_old != KCH - 1) return;
    __threadfence();

    for (int idx = tid; idx < 32 * WB; idx += 256) {
        int rl = idx / WB, c = idx - rl * WB;
        int r = i0 + rl, p = r + c - BAND;
        float d = 0.f;
        if ((unsigned)p < NN) {
            float dot = __ldcg(&g_dpart[(size_t)r * WB + c])
                      + __ldcg(&g_dpart[(size_t)(NN + r) * WB + c])
                      + __ldcg(&g_dpart[(size_t)(2 * NN + r) * WB + c])
                      + __ldcg(&g_dpart[(size_t)(3 * NN + r) * WB + c]);
            d = g_xsq[r] + g_ysq[p] - 2.0f * dot;
        }
        g_dband[(size_t)r * WB + c] = d;
        if (c == BAND) {
            double la = g_lps[BAND] - (double)d * K2;
            g_la[r] = la;
            sla[rl] = la;
        }
    }
    __syncthreads();
    for (int idx = tid; idx < 32 * WB; idx += 256) {
        int rl = idx / WB, c = idx - rl * WB;
        int r = i0 + rl, p = r + c - BAND;
        float val = 0.f;
        if ((unsigned)p < NN) {
            double arg = g_lps[c] - (double)g_dband[(size_t)r * WB + c] * K2 - sla[rl];
            val = exp2f((float)arg);
        }
        g_kbR[(size_t)r * WB + c] = val;
        g_kbC[(size_t)c * NN + r] = val;
        if ((unsigned)p < NN) g_kbTC[(size_t)(2 * BAND - c) * NN + p] = val;
        else                  g_kbTC[(size_t)c * NN + r] = 0.f;
    }
}

// ---------------- half-row smem dots (cols 0..24 and 25..48) ----------------
__device__ __forceinline__ float sdot25(const float* __restrict__ kr,
                                        const float* __restrict__ uw) {
    float a0 = 0.f, a1 = 0.f;
#pragma unroll
    for (int c = 0; c < 24; c += 2) {
        a0 = fmaf(kr[c + 0], uw[c + 0], a0);
        a1 = fmaf(kr[c + 1], uw[c + 1], a1);
    }
    a0 = fmaf(kr[24], uw[24], a0);
    return a0 + a1;
}
__device__ __forceinline__ float sdot24(const float* __restrict__ kr,
                                        const float* __restrict__ uw) {
    float a0 = 0.f, a1 = 0.f;
#pragma unroll
    for (int c = 0; c < 24; c += 2) {
        a0 = fmaf(kr[c + 0], uw[c + 0], a0);
        a1 = fmaf(kr[c + 1], uw[c + 1], a1);
    }
    return a0 + a1;
}

// ---------------- L4: cluster Sinkhorn — 2 threads/row, smem kappa, DSMEM halo ----------------
extern __shared__ float sdyn[];
__global__ void __launch_bounds__(STPB, 1) __cluster_dims__(NCL, 1, 1)
sink_k() {
    const int tid = threadIdx.x;
    const int rk = (int)ctarank();
    const int R0 = rk * RPC;
    const int half = tid & 1;       // 0: cols 0..24, 1: cols 25..48
    const int r2 = tid >> 1;        // row 0..255
    float* sKT = sdyn;              // [EXT][49]
    float* sKB = sdyn + SKT_SZ;     // [RPC][49]
    __shared__ float su[2][WIN];    // u rows [R0-48, R0+304), double-buffered
    __shared__ float sv[EXT];       // v rows [R0-24, R0+280)
    __shared__ float sw[EXT];
    __shared__ double sred[STPB];
    __shared__ unsigned long long mbar_s;
    const uint32_t mb = smem_u32(&mbar_s);

    if (tid == 0) {
        int expect = (rk > 0 ? 48 : 0) + (rk < NCL - 1 ? 48 : 0);
        MBAR_INIT(mb, expect);
    }
    for (int q = tid; q < 2 * WIN; q += STPB) ((float*)su)[q] = 0.f;
    // preload kappa slices
    for (int idx = tid; idx < SKT_SZ; idx += STPB) {
        int c = idx / EXT, t = idx - c * EXT;
        int row = R0 - 24 + t;
        sKT[t * WB + c] = ((unsigned)row < NN) ? __ldcg(&g_kbTC[(size_t)c * NN + row]) : 0.f;
    }
    for (int idx = tid; idx < SKB_SZ; idx += STPB) {
        int c = idx >> 8, t = idx & 255;
        sKB[t * WB + c] = __ldcg(&g_kbC[(size_t)c * NN + R0 + t]);
    }
    double myla = g_la[R0 + r2], la0 = g_la[0];
    __syncthreads();
    CLUSTER_SYNC();                 // barriers + zeroed windows visible cluster-wide

    int ev = 0;                     // index of last published u event

    // split-dot for one row: both halves compute, shfl_xor(1) combines; both get full sum
    auto rowdotT = [&](const float* kr, const float* uw) -> float {
        float p = half ? sdot24(kr + 25, uw + 25) : sdot25(kr, uw);
        float q = __shfl_xor_sync(0xffffffffu, p, 1);
        return p + q;               // addition commutative -> identical in both halves
    };

    // publish u value for row R0+r2 (half0 only) into buffer `buf`, push halo
    auto PUBLISH = [&](int buf, float val) {
        if (half == 0) {
            su[buf][48 + r2] = val;
            if (rk > 0 && r2 < 48)
                PUSH_ARRIVE(smem_u32(&su[buf][304 + r2]), mb, rk - 1, val);
            if (rk < NCL - 1 && r2 >= 208)
                PUSH_ARRIVE(smem_u32(&su[buf][r2 - 208]), mb, rk + 1, val);
        }
    };
    auto WAITEV = [&]() {
        if (tid == 0) TRYWAIT_PAR(mb, ev & 1);
        __syncthreads();
    };
    // v = b/(kT u_ev) over ext rows (write to dst); 2 threads per row
    auto AEXT = [&](float* dst, int inv) {
        const float* ub = su[ev & 1];
        {
            int t = r2, j = R0 - 24 + t;
            float s = rowdotT(sKT + t * WB, ub + t);
            if (half == 0) dst[t] = ((unsigned)j < NN) ? (inv ? INV_M / s : s) : 0.f;
        }
        if (tid < 96) {
            int t = 256 + (tid >> 1), j = R0 - 24 + t;
            float s = rowdotT(sKT + t * WB, ub + t);
            if (half == 0) dst[t] = ((unsigned)j < NN) ? (inv ? INV_M / s : s) : 0.f;
        }
        __syncthreads();
    };
    auto FUSED = [&]() {
        WAITEV();
        AEXT(sv, 1);
        float s = rowdotT(sKB + r2 * WB, sv + r2);
        float un = 1.0f / ((float)NN * s);
        ev++;
        PUBLISH(ev & 1, un);
    };

    // event 0: u0 = a_i/a_0 (lambda-rescaled init; iteration is lambda-invariant)
    PUBLISH(0, exp2f((float)(myla - la0)));
    FUSED();                        // u1 (ev=1)
    FUSED();                        // v2 in sv, u2 (ev=2)

    // crit: w = kT u2 ext (sv preserved); partial |v2*w - 1/m| on own rows
    WAITEV();
    AEXT(sw, 0);
    sred[tid] = (half == 0)
        ? fabs((double)sv[r2 + 24] * (double)sw[r2 + 24] - 1.0 / (double)MM) : 0.0;
    __syncthreads();
    for (int o = 256; o; o >>= 1) { if (tid < o) sred[tid] += sred[tid + o]; __syncthreads(); }
    if (tid == 0) g_part[rk] = sred[0];
    __threadfence();
    CLUSTER_SYNC();
    double crit = 0.0;
    for (int q = 0; q < NCL; q++) crit += __ldcg(&g_part[q]);
    int done = ((crit < 0.005) || (crit != crit)) ? 1 : 0;

    if (!done) {
        // plain update 1: v3 = b/w (ext, local), u3 (ev=3)
        for (int t = tid; t < EXT; t += STPB) {
            int j = R0 - 24 + t;
            sv[t] = ((unsigned)j < NN) ? INV_M / sw[t] : 0.f;
        }
        __syncthreads();
        float s = rowdotT(sKB + r2 * WB, sv + r2);
        float un = 1.0f / ((float)NN * s);
        ev++;                       // ev = 3
        PUBLISH(ev & 1, un);
        for (int it = 0; it < 18; it++) FUSED();   // 17 plain + final special; ev = 21
    }

    CLUSTER_SYNC();                 // all inbound pushes landed; safe to export+exit
    if (half == 0) {
        g_u[R0 + r2] = su[ev & 1][48 + r2];
        g_v[R0 + r2] = sv[r2 + 24];
    }
}

// ---------------- L5: full-chip finalize: t rows + dis (last-arriver) ----------------
__global__ void finalize_k(float* __restrict__ tbase, float* __restrict__ disp) {
    int bid = blockIdx.x, tid = threadIdx.x;          // 256 blocks x 256 threads
    double dp = 0.0;
    for (int rl = 0; rl < 8; rl++) {
        int i = bid * 8 + rl;
        float ui = g_u[i];
        const float* kr = g_kbR + (size_t)i * WB;
        const float* dr = g_dband + (size_t)i * WB;
        if (tbase) {
            float* orow = tbase + (size_t)i * MM;
            for (int j = tid; j < MM; j += 256) {
                int c = j - i + BAND;
                float tv = 0.f;
                if ((unsigned)c < WB) {
                    tv = ui * __ldg(&kr[c]) * g_v[j];
                    dp += (double)tv * (double)__ldg(&dr[c]);
                }
                orow[j] = tv;
            }
        } else {
            for (int j = tid; j < MM; j += 256) {
                int c = j - i + BAND;
                if ((unsigned)c < WB)
                    dp += (double)(ui * __ldg(&kr[c]) * g_v[j]) * (double)__ldg(&dr[c]);
            }
        }
    }
    __shared__ double sh[256];
    __shared__ int s_last;
    sh[tid] = dp; __syncthreads();
    for (int o = 128; o; o >>= 1) { if (tid < o) sh[tid] += sh[tid + o]; __syncthreads(); }
    if (tid == 0) g_part2[bid] = sh[0];
    __threadfence();
    __syncthreads();
    if (tid == 0) s_last = atomicAdd(&g_fincnt, 1);
    __syncthreads();
    if (s_last != 255) return;
    __threadfence();
    sh[tid] = __ldcg(&g_part2[tid]);
    __syncthreads();
    for (int o = 128; o; o >>= 1) { if (tid < o) sh[tid] += sh[tid + o]; __syncthreads(); }
    if (tid == 0 && disp) disp[0] = (float)sh[0];
}

// ---------------- host ----------------
extern "C" void kernel_launch(void* const* d_in, const int* in_sizes, int n_in,
                              void* d_out, int out_size) {
    (void)in_sizes; (void)n_in;
    const float* X = (const float*)d_in[0];
    const float* Y = (const float*)d_in[1];

    cudaFuncSetAttribute(sink_k, cudaFuncAttributeMaxDynamicSharedMemorySize, SMEM_DYN);

    colstats_k <<<dim3(DD / 32, 2), dim3(32, 16)>>>(X, Y);
    normrow_k  <<<dim3(NN, 2), 256>>>(X, Y);
    band_gemm_k<<<dim3(NTILE, KCH), 256>>>();
    sink_k     <<<NCL, STPB, SMEM_DYN>>>();

    float* out = (float*)d_out;
    long long total = (long long)NN * (long long)MM;
    float* tbase = 0;
    float* disp  = 0;
    if ((long long)out_size == total + 1) { disp = out; tbase = out + 1; }
    else if ((long long)out_size >= total) { tbase = out; }
    else { disp = out; }

    finalize_k<<<256, 256>>>(tbase, disp);
}

// round 16
// speedup vs baseline: 1.0986x; 1.0986x over previous
#include <cuda_runtime.h>
#include <math.h>
#include <stdint.h>

#define NN 2048
#define MM 2048
#define DD 1024
#define BAND 24
#define WB 49             // 2*BAND+1; f32 kappa support is |i-j| <~ 22
#define KCH 4
#define KLEN (DD / KCH)   // 256
#define NTILE (NN / 32)   // 64 GEMM row-tiles
#define NCL 8             // cluster CTAs
#define RPC 256           // rows per cluster CTA
#define EXT 304           // extended v/w rows per CTA [R0-24, R0+280)
#define WIN 352           // u window rows [R0-48, R0+304)
#define STPB 384          // sink threads per CTA (12 warps)
#define SKT_SZ (EXT * WB) // 14896 floats
#define SKB_SZ (RPC * WB) // 12544 floats
#define SMEM_DYN ((SKT_SZ + SKB_SZ) * 4)

#define LOG2E    1.4426950408889634074
#define K2       14.426950408889634074    // 10*log2(e)
#define L2ISQ2PI (-1.3257480647361593)    // log2(1/sqrt(2*pi))
#define INV_M    (1.0f / 2048.0f)

// ---------------- scratch ----------------
__device__ __align__(16) float  g_cx[DD], g_cy[DD];
__device__ __align__(16) float  g_Xn[NN * DD];
__device__ __align__(16) float  g_Yn[MM * DD];
__device__ __align__(16) float  g_xsq[NN], g_ysq[MM];
__device__ __align__(16) float  g_dpart[KCH * NN * WB];
__device__ __align__(16) float  g_dband[NN * WB];     // row-major d[i][c], j = i + c - BAND
__device__ __align__(16) float  g_kbC [WB * NN];      // kappa[i][c]  at [c*NN + i] (col-major)
__device__ __align__(16) float  g_kbTC[WB * NN];      // kappaT[j][c] at [c*NN + j] (col-major)
__device__ __align__(16) float  g_kbR [NN * WB];      // kappa row-major (finalize)
__device__ __align__(16) double g_lps[WB];
__device__ double g_la[NN];
__device__ float  g_u[NN], g_v[NN];
__device__ double g_part[NCL], g_part2[256];
__device__ int    g_tilecnt[NTILE];
__device__ int    g_fincnt;

#define CLUSTER_SYNC() do { \
    asm volatile("barrier.cluster.arrive.aligned;" ::: "memory"); \
    asm volatile("barrier.cluster.wait.aligned;"   ::: "memory"); } while (0)

__device__ __forceinline__ unsigned ctarank() {
    unsigned r; asm("mov.u32 %0, %%cluster_ctarank;" : "=r"(r)); return r;
}
__device__ __forceinline__ uint32_t smem_u32(const void* p) {
    uint32_t a;
    asm("{ .reg .u64 t; cvta.to.shared.u64 t, %1; cvt.u32.u64 %0, t; }" : "=r"(a) : "l"(p));
    return a;
}
#define MBAR_INIT(addr, cnt) \
    asm volatile("mbarrier.init.shared.b64 [%0], %1;" :: "r"(addr), "r"(cnt) : "memory")
// push one f32 into the same smem offset of CTA `rank`, then release-arrive on its barrier
#define PUSH_ARRIVE(slot_addr, mbar_addr, rank, val) \
    asm volatile("{ .reg .b32 ra, rb;\n\t" \
                 "mapa.shared::cluster.u32 ra, %0, %2;\n\t" \
                 "st.shared::cluster.f32 [ra], %3;\n\t" \
                 "mapa.shared::cluster.u32 rb, %1, %2;\n\t" \
                 "mbarrier.arrive.release.cluster.shared::cluster.b64 _, [rb];\n\t}" \
                 :: "r"(slot_addr), "r"(mbar_addr), "r"(rank), "f"(val) : "memory")
#define TRYWAIT_PAR(mbar_addr, par) do { \
    unsigned done_ = 0; \
    while (!done_) { \
        asm volatile("{ .reg .pred p;\n\t" \
                     "mbarrier.try_wait.parity.acquire.cluster.shared::cta.b64 p, [%1], %2, 0x989680;\n\t" \
                     "selp.b32 %0, 1, 0, p;\n\t}" \
                     : "=r"(done_) : "r"(mbar_addr), "r"((unsigned)(par)) : "memory"); \
    } } while (0)
#define BARSYNC96() asm volatile("bar.sync 1, 96;" ::: "memory")

// ---------------- L1: column stats (X and Y) + init ----------------
__global__ void colstats_k(const float* __restrict__ X, const float* __restrict__ Y) {
    int lt = threadIdx.y * 32 + threadIdx.x;
    if (blockIdx.x == 0 && blockIdx.y == 0) {
        if (lt < NTILE) g_tilecnt[lt] = 0;
        if (lt == 0)    g_fincnt = 0;
        if (lt < WB) {
            double off = (double)(BAND - lt);
            double di  = off / (double)NN;
            double l2p = -(off * off * 0.25) * LOG2E + L2ISQ2PI;
            double s   = 50.0 / (di * di + 1.0);
            g_lps[lt] = l2p + s * K2;
        }
    }
    const float* A = blockIdx.y ? Y : X;
    int col = blockIdx.x * 32 + threadIdx.x;
    double s = 0.0, s2 = 0.0;
#pragma unroll 4
    for (int r = threadIdx.y; r < NN; r += 8) {
        double v = (double)A[r * DD + col];
        s += v; s2 += v * v;
    }
    __shared__ double shs[8][32], shs2[8][32];
    shs[threadIdx.y][threadIdx.x] = s;
    shs2[threadIdx.y][threadIdx.x] = s2;
    __syncthreads();
    if (threadIdx.y == 0) {
        for (int y = 1; y < 8; y++) { s += shs[y][threadIdx.x]; s2 += shs2[y][threadIdx.x]; }
        double mean = s / (double)NN;
        double var  = (s2 - (double)NN * mean * mean) / (double)(NN - 1);
        float  c    = (float)(mean / sqrt(var + 1e-4));
        (blockIdx.y ? g_cy : g_cx)[col] = c;
    }
}

// ---------------- L2: fused normalize + row squared norm ----------------
__global__ void normrow_k(const float* __restrict__ X, const float* __restrict__ Y) {
    int isY = blockIdx.y;
    const float* A = isY ? Y : X;
    const float* C = isY ? g_cy : g_cx;
    float* O       = isY ? g_Yn : g_Xn;
    int r = blockIdx.x, t = threadIdx.x;             // 256 threads
    float4 a = ((const float4*)(A + (size_t)r * DD))[t];
    float4 c = ((const float4*)C)[t];
    float4 o = make_float4(a.x - c.x, a.y - c.y, a.z - c.z, a.w - c.w);
    ((float4*)(O + (size_t)r * DD))[t] = o;
    double s = (double)o.x * o.x + (double)o.y * o.y + (double)o.z * o.z + (double)o.w * o.w;
    __shared__ double sh[256];
    sh[t] = s; __syncthreads();
    for (int off = 128; off > 0; off >>= 1) {
        if (t < off) sh[t] += sh[t + off];
        __syncthreads();
    }
    if (t == 0) (isY ? g_ysq : g_xsq)[r] = (float)sh[0];
}

// ---------------- L3: band GEMM (split-K x4) + fused d/la/kappa epilogue ----------------
__global__ void band_gemm_k() {
    int ti = blockIdx.x;
    int i0 = ti * 32;
    int j0 = i0 - 32;
    int cz = blockIdx.y;

    __shared__ float Xs[32][33];
    __shared__ float Ys[96][33];
    int tid = threadIdx.x;                           // 256 threads
    int tx = tid & 31, ty = tid >> 5;
    float acc[4][3];
#pragma unroll
    for (int a = 0; a < 4; a++)
#pragma unroll
        for (int bb = 0; bb < 3; bb++) acc[a][bb] = 0.f;

    for (int k0 = 0; k0 < KLEN; k0 += 32) {
        {
            int r = tid >> 3, q = tid & 7;
            float4 v = *(const float4*)(g_Xn + (size_t)(i0 + r) * DD + cz * KLEN + k0 + q * 4);
            Xs[r][q * 4 + 0] = v.x; Xs[r][q * 4 + 1] = v.y;
            Xs[r][q * 4 + 2] = v.z; Xs[r][q * 4 + 3] = v.w;
        }
#pragma unroll
        for (int l = 0; l < 3; l++) {
            int li = tid + l * 256;
            int r = li >> 3, q = li & 7;
            int gj = j0 + r;
            float4 v = make_float4(0.f, 0.f, 0.f, 0.f);
            if ((unsigned)gj < NN)
                v = *(const float4*)(g_Yn + (size_t)gj * DD + cz * KLEN + k0 + q * 4);
            Ys[r][q * 4 + 0] = v.x; Ys[r][q * 4 + 1] = v.y;
            Ys[r][q * 4 + 2] = v.z; Ys[r][q * 4 + 3] = v.w;
        }
        __syncthreads();
#pragma unroll
        for (int kk = 0; kk < 32; kk++) {
            float av[4], bv[3];
#pragma unroll
            for (int a = 0; a < 4; a++) av[a] = Xs[ty * 4 + a][kk];
#pragma unroll
            for (int bb = 0; bb < 3; bb++) bv[bb] = Ys[tx * 3 + bb][kk];
#pragma unroll
            for (int a = 0; a < 4; a++)
#pragma unroll
                for (int bb = 0; bb < 3; bb++) acc[a][bb] += av[a] * bv[bb];
        }
        __syncthreads();
    }

#pragma unroll
    for (int a = 0; a < 4; a++) {
        int gi = i0 + ty * 4 + a;
#pragma unroll
        for (int bb = 0; bb < 3; bb++) {
            int gj = j0 + tx * 3 + bb;
            int c = gj - gi + BAND;
            if ((unsigned)gj < NN && c >= 0 && c < WB)
                g_dpart[((size_t)cz * NN + gi) * WB + c] = acc[a][bb];
        }
    }

    // split-K fixup: last arriver runs the epilogue (deterministic math)
    __shared__ int s_old;
    __shared__ double sla[32];
    __threadfence();
    __syncthreads();
    if (tid == 0) s_old = atomicAdd(&g_tilecnt[ti], 1);
    __syncthreads();
    if (s_old != KCH - 1) return;
    __threadfence();

    for (int idx = tid; idx < 32 * WB; idx += 256) {
        int rl = idx / WB, c = idx - rl * WB;
        int r = i0 + rl, p = r + c - BAND;
        float d = 0.f;
        if ((unsigned)p < NN) {
            float dot = __ldcg(&g_dpart[(size_t)r * WB + c])
                      + __ldcg(&g_dpart[(size_t)(NN + r) * WB + c])
                      + __ldcg(&g_dpart[(size_t)(2 * NN + r) * WB + c])
                      + __ldcg(&g_dpart[(size_t)(3 * NN + r) * WB + c]);
            d = g_xsq[r] + g_ysq[p] - 2.0f * dot;
        }
        g_dband[(size_t)r * WB + c] = d;
        if (c == BAND) {
            double la = g_lps[BAND] - (double)d * K2;
            g_la[r] = la;
            sla[rl] = la;
        }
    }
    __syncthreads();
    for (int idx = tid; idx < 32 * WB; idx += 256) {
        int rl = idx / WB, c = idx - rl * WB;
        int r = i0 + rl, p = r + c - BAND;
        float val = 0.f;
        if ((unsigned)p < NN) {
            double arg = g_lps[c] - (double)g_dband[(size_t)r * WB + c] * K2 - sla[rl];
            val = exp2f((float)arg);
        }
        g_kbR[(size_t)r * WB + c] = val;
        g_kbC[(size_t)c * NN + r] = val;
        if ((unsigned)p < NN) g_kbTC[(size_t)(2 * BAND - c) * NN + p] = val;
        else                  g_kbTC[(size_t)c * NN + r] = 0.f;
    }
}

// ---------------- smem banded dot (stride-49 rows: conflict-free) ----------------
__device__ __forceinline__ float sdot49(const float* __restrict__ kr,
                                        const float* __restrict__ uw) {
    float a0 = 0.f, a1 = 0.f, a2 = 0.f, a3 = 0.f;
#pragma unroll
    for (int c = 0; c < 48; c += 4) {
        a0 = fmaf(kr[c + 0], uw[c + 0], a0);
        a1 = fmaf(kr[c + 1], uw[c + 1], a1);
        a2 = fmaf(kr[c + 2], uw[c + 2], a2);
        a3 = fmaf(kr[c + 3], uw[c + 3], a3);
    }
    a0 = fmaf(kr[48], uw[48], a0);
    return (a0 + a1) + (a2 + a3);
}

// ---------------- L4: cluster Sinkhorn — boundary/interior pipelined events ----------------
// Row->thread maps: boundary u rows {0..47}->tid 0..47, {208..255}->tid 48..95;
// interior u rows {48..207}->tid 96..255. Boundary v t in {0..47}u{256..303}->tid 0..95;
// interior v t in {48..255}->tid 96..303.
extern __shared__ float sdyn[];
__global__ void __launch_bounds__(STPB, 1) __cluster_dims__(NCL, 1, 1)
sink_k() {
    const int tid = threadIdx.x;
    const int rk = (int)ctarank();
    const int R0 = rk * RPC;
    float* sKT = sdyn;              // [EXT][49]
    float* sKB = sdyn + SKT_SZ;     // [RPC][49]
    __shared__ float su[2][WIN];    // u rows [R0-48, R0+304), double-buffered
    __shared__ float sv[EXT];       // v rows [R0-24, R0+280)
    __shared__ float sw[EXT];
    __shared__ double sred[512];
    __shared__ unsigned long long mbar_s;
    const uint32_t mb = smem_u32(&mbar_s);

    const int urow = (tid < 48) ? tid : (tid < 96 ? 160 + tid : (tid < 256 ? tid - 48 : -1));

    if (tid == 0) {
        int expect = (rk > 0 ? 48 : 0) + (rk < NCL - 1 ? 48 : 0);
        MBAR_INIT(mb, expect);
    }
    for (int q = tid; q < 2 * WIN; q += STPB) ((float*)su)[q] = 0.f;
    if (tid < 128) sred[384 + tid] = 0.0;
    // preload kappa slices (conflict-free smem scatter; 49 odd)
    for (int idx = tid; idx < SKT_SZ; idx += STPB) {
        int c = idx / EXT, t = idx - c * EXT;
        int row = R0 - 24 + t;
        sKT[t * WB + c] = ((unsigned)row < NN) ? __ldcg(&g_kbTC[(size_t)c * NN + row]) : 0.f;
    }
    for (int idx = tid; idx < SKB_SZ; idx += STPB) {
        int c = idx >> 8, t = idx & 255;
        sKB[t * WB + c] = __ldcg(&g_kbC[(size_t)c * NN + R0 + t]);
    }
    double la0 = g_la[0];
    double myla = (urow >= 0) ? g_la[R0 + urow] : 0.0;
    __syncthreads();
    CLUSTER_SYNC();                 // barriers + zeroed windows visible cluster-wide

    int ev = 0;                     // index of last published u event

    // store own u + halo pushes (caller supplies buffer index nb)
    auto PUBLISH = [&](int nb, float val) {
        su[nb][48 + urow] = val;
        if (rk > 0 && urow < 48)
            PUSH_ARRIVE(smem_u32(&su[nb][304 + urow]), mb, rk - 1, val);
        if (rk < NCL - 1 && urow >= 208)
            PUSH_ARRIVE(smem_u32(&su[nb][urow - 208]), mb, rk + 1, val);
    };
    // one full iteration: v = b/(kT u_ev); u_{ev+1} = 1/(n k v); boundary overlapped
    auto FUSED = [&]() {
        const float* ub = su[ev & 1];
        if (tid >= 96 && tid < 304) {               // interior v, no halo dependency
            int t = tid - 48;                       // 48..255 (j always valid)
            sv[t] = INV_M / sdot49(sKT + t * WB, ub + t);
        } else if (tid < 96) {                      // boundary v after halo wait
            if (tid == 0) TRYWAIT_PAR(mb, ev & 1);
            BARSYNC96();
            int t = (tid < 48) ? tid : 208 + tid;   // 0..47, 256..303
            int j = R0 - 24 + t;
            sv[t] = ((unsigned)j < NN) ? INV_M / sdot49(sKT + t * WB, ub + t) : 0.f;
        }
        __syncthreads();
        int nb = (ev + 1) & 1;
        if (tid < 256) {                            // boundary u first (tid<96) -> push early
            float un = 1.0f / ((float)NN * sdot49(sKB + urow * WB, sv + urow));
            PUBLISH(nb, un);
        }
        ev++;
        __syncthreads();
    };

    // event 0: u0 = a_i/a_0 (lambda-rescaled init; iteration is lambda-invariant)
    if (urow >= 0) PUBLISH(0, exp2f((float)(myla - la0)));
    __syncthreads();
    FUSED();                        // u1 (ev=1)
    FUSED();                        // v2 in sv, u2 (ev=2)

    // crit: w = kT u2 over ext rows (sv preserved); same interior/boundary split
    {
        const float* ub = su[ev & 1];
        if (tid >= 96 && tid < 304) {
            int t = tid - 48;
            sw[t] = sdot49(sKT + t * WB, ub + t);
        } else if (tid < 96) {
            if (tid == 0) TRYWAIT_PAR(mb, ev & 1);
            BARSYNC96();
            int t = (tid < 48) ? tid : 208 + tid;
            int j = R0 - 24 + t;
            sw[t] = ((unsigned)j < NN) ? sdot49(sKT + t * WB, ub + t) : 0.f;
        }
    }
    __syncthreads();
    sred[tid] = (tid < 256)
        ? fabs((double)sv[tid + 24] * (double)sw[tid + 24] - 1.0 / (double)MM) : 0.0;
    __syncthreads();
    for (int o = 256; o; o >>= 1) { if (tid < o) sred[tid] += sred[tid + o]; __syncthreads(); }
    if (tid == 0) g_part[rk] = sred[0];
    __threadfence();
    CLUSTER_SYNC();
    double crit = 0.0;
    for (int q = 0; q < NCL; q++) crit += __ldcg(&g_part[q]);
    int done = ((crit < 0.005) || (crit != crit)) ? 1 : 0;

    if (!done) {
        // plain update 1: v3 = b/w (local), u3 (ev=3)
        for (int t = tid; t < EXT; t += STPB) {
            int j = R0 - 24 + t;
            sv[t] = ((unsigned)j < NN) ? INV_M / sw[t] : 0.f;
        }
        __syncthreads();
        int nb = (ev + 1) & 1;
        if (tid < 256) {
            float un = 1.0f / ((float)NN * sdot49(sKB + urow * WB, sv + urow));
            PUBLISH(nb, un);
        }
        ev++;
        __syncthreads();
        for (int it = 0; it < 18; it++) FUSED();   // 17 plain + final special; ev = 21
    }

    CLUSTER_SYNC();                 // all inbound pushes landed; safe to export+exit
    if (tid < 256) {
        g_u[R0 + tid] = su[ev & 1][48 + tid];
        g_v[R0 + tid] = sv[tid + 24];
    }
}

// ---------------- L5: full-chip finalize: t rows + dis (last-arriver) ----------------
__global__ void finalize_k(float* __restrict__ tbase, float* __restrict__ disp) {
    int bid = blockIdx.x, tid = threadIdx.x;          // 256 blocks x 256 threads
    double dp = 0.0;
    for (int rl = 0; rl < 8; rl++) {
        int i = bid * 8 + rl;
        float ui = g_u[i];
        const float* kr = g_kbR + (size_t)i * WB;
        const float* dr = g_dband + (size_t)i * WB;
        if (tbase) {
            float* orow = tbase + (size_t)i * MM;
            for (int j = tid; j < MM; j += 256) {
                int c = j - i + BAND;
                float tv = 0.f;
                if ((unsigned)c < WB) {
                    tv = ui * __ldg(&kr[c]) * g_v[j];
                    dp += (double)tv * (double)__ldg(&dr[c]);
                }
                orow[j] = tv;
            }
        } else {
            for (int j = tid; j < MM; j += 256) {
                int c = j - i + BAND;
                if ((unsigned)c < WB)
                    dp += (double)(ui * __ldg(&kr[c]) * g_v[j]) * (double)__ldg(&dr[c]);
            }
        }
    }
    __shared__ double sh[256];
    __shared__ int s_last;
    sh[tid] = dp; __syncthreads();
    for (int o = 128; o; o >>= 1) { if (tid < o) sh[tid] += sh[tid + o]; __syncthreads(); }
    if (tid == 0) g_part2[bid] = sh[0];
    __threadfence();
    __syncthreads();
    if (tid == 0) s_last = atomicAdd(&g_fincnt, 1);
    __syncthreads();
    if (s_last != 255) return;
    __threadfence();
    sh[tid] = __ldcg(&g_part2[tid]);
    __syncthreads();
    for (int o = 128; o; o >>= 1) { if (tid < o) sh[tid] += sh[tid + o]; __syncthreads(); }
    if (tid == 0 && disp) disp[0] = (float)sh[0];
}

// ---------------- host ----------------
extern "C" void kernel_launch(void* const* d_in, const int* in_sizes, int n_in,
                              void* d_out, int out_size) {
    (void)in_sizes; (void)n_in;
    const float* X = (const float*)d_in[0];
    const float* Y = (const float*)d_in[1];

    cudaFuncSetAttribute(sink_k, cudaFuncAttributeMaxDynamicSharedMemorySize, SMEM_DYN);

    colstats_k <<<dim3(DD / 32, 2), dim3(32, 8)>>>(X, Y);
    normrow_k  <<<dim3(NN, 2), 256>>>(X, Y);
    band_gemm_k<<<dim3(NTILE, KCH), 256>>>();
    sink_k     <<<NCL, STPB, SMEM_DYN>>>();

    float* out = (float*)d_out;
    long long total = (long long)NN * (long long)MM;
    float* tbase = 0;
    float* disp  = 0;
    if ((long long)out_size == total + 1) { disp = out; tbase = out + 1; }
    else if ((long long)out_size >= total) { tbase = out; }
    else { disp = out; }

    finalize_k<<<256, 256>>>(tbase, disp);
}

// round 17
// speedup vs baseline: 1.3886x; 1.2640x over previous
#include <cuda_runtime.h>
#include <math.h>
#include <stdint.h>

#define NN 2048
#define MM 2048
#define DD 1024
#define BAND 24
#define WB 49             // 2*BAND+1; f32 kappa support is |i-j| <~ 22
#define KCH 8
#define KLEN (DD / KCH)   // 128
#define NTILE (NN / 32)   // 64 GEMM row-tiles
#define NCL 8             // cluster CTAs
#define RPC 256           // rows per cluster CTA
#define EXT 304           // extended v/w rows per CTA [R0-24, R0+280)
#define WIN 352           // u window rows [R0-48, R0+304)
#define STPB 640          // sink threads (304 v-rows + 256 u-rows + pad)
#define ZCH 8             // colstats row chunks

#define LOG2E    1.4426950408889634074
#define K2       14.426950408889634074    // 10*log2(e)
#define L2ISQ2PI (-1.3257480647361593)    // log2(1/sqrt(2*pi))
#define INV_M    (1.0f / 2048.0f)

// ---------------- scratch ----------------
__device__ __align__(16) float  g_cx[DD], g_cy[DD];
__device__ __align__(16) double g_cps [2][ZCH][DD];
__device__ __align__(16) double g_cps2[2][ZCH][DD];
__device__ __align__(16) float  g_Xn[NN * DD];
__device__ __align__(16) float  g_Yn[MM * DD];
__device__ __align__(16) float  g_xsq[NN], g_ysq[MM];
__device__ __align__(16) float  g_dpart[KCH * NN * WB];
__device__ __align__(16) float  g_dband[NN * WB];     // row-major d[i][c], j = i + c - BAND
__device__ __align__(16) float  g_kbC [WB * NN];      // kappa[i][c]  at [c*NN + i] (col-major)
__device__ __align__(16) float  g_kbTC[WB * NN];      // kappaT[j][c] at [c*NN + j] (col-major)
__device__ __align__(16) float  g_kbR [NN * WB];      // kappa row-major (finalize)
__device__ __align__(16) double g_lps[WB];
__device__ double g_la[NN];
__device__ float  g_u[NN], g_v[NN];
__device__ double g_part[NCL], g_part2[256];
__device__ int    g_tilecnt[NTILE];
__device__ int    g_fincnt;

#define CLUSTER_SYNC() do { \
    asm volatile("barrier.cluster.arrive.aligned;" ::: "memory"); \
    asm volatile("barrier.cluster.wait.aligned;"   ::: "memory"); } while (0)

__device__ __forceinline__ unsigned ctarank() {
    unsigned r; asm("mov.u32 %0, %%cluster_ctarank;" : "=r"(r)); return r;
}
__device__ __forceinline__ uint32_t smem_u32(const void* p) {
    uint32_t a;
    asm("{ .reg .u64 t; cvta.to.shared.u64 t, %1; cvt.u32.u64 %0, t; }" : "=r"(a) : "l"(p));
    return a;
}
#define MBAR_INIT(addr, cnt) \
    asm volatile("mbarrier.init.shared.b64 [%0], %1;" :: "r"(addr), "r"(cnt) : "memory")
#define PUSH_ARRIVE(slot_addr, mbar_addr, rank, val) \
    asm volatile("{ .reg .b32 ra, rb;\n\t" \
                 "mapa.shared::cluster.u32 ra, %0, %2;\n\t" \
                 "st.shared::cluster.f32 [ra], %3;\n\t" \
                 "mapa.shared::cluster.u32 rb, %1, %2;\n\t" \
                 "mbarrier.arrive.release.cluster.shared::cluster.b64 _, [rb];\n\t}" \
                 :: "r"(slot_addr), "r"(mbar_addr), "r"(rank), "f"(val) : "memory")
#define TRYWAIT_PAR(mbar_addr, par) do { \
    unsigned done_ = 0; \
    while (!done_) { \
        asm volatile("{ .reg .pred p;\n\t" \
                     "mbarrier.try_wait.parity.acquire.cluster.shared::cta.b64 p, [%1], %2, 0x989680;\n\t" \
                     "selp.b32 %0, 1, 0, p;\n\t}" \
                     : "=r"(done_) : "r"(mbar_addr), "r"((unsigned)(par)) : "memory"); \
    } } while (0)
#define BARSYNC96() asm volatile("bar.sync 1, 96;" ::: "memory")

// ---------------- L1a: column stats partials (X and Y, 8 row-chunks) + init ----------------
__global__ void colstats_part_k(const float* __restrict__ X, const float* __restrict__ Y) {
    int lt = threadIdx.y * 32 + threadIdx.x;
    if (blockIdx.x == 0 && blockIdx.y == 0 && blockIdx.z == 0) {
        if (lt < NTILE) g_tilecnt[lt] = 0;
        if (lt == 0)    g_fincnt = 0;
        if (lt < WB) {
            double off = (double)(BAND - lt);
            double di  = off / (double)NN;
            double l2p = -(off * off * 0.25) * LOG2E + L2ISQ2PI;
            double s   = 50.0 / (di * di + 1.0);
            g_lps[lt] = l2p + s * K2;
        }
    }
    const float* A = blockIdx.y ? Y : X;
    int col = blockIdx.x * 32 + threadIdx.x;
    int z = blockIdx.z;
    int rbase = z * (NN / ZCH);
    double s = 0.0, s2 = 0.0;
#pragma unroll 8
    for (int r = threadIdx.y; r < NN / ZCH; r += 8) {
        double v = (double)A[(size_t)(rbase + r) * DD + col];
        s += v; s2 += v * v;
    }
    __shared__ double shs[8][32], shs2[8][32];
    shs[threadIdx.y][threadIdx.x] = s;
    shs2[threadIdx.y][threadIdx.x] = s2;
    __syncthreads();
    if (threadIdx.y == 0) {
        for (int y = 1; y < 8; y++) { s += shs[y][threadIdx.x]; s2 += shs2[y][threadIdx.x]; }
        g_cps [blockIdx.y][z][col] = s;
        g_cps2[blockIdx.y][z][col] = s2;
    }
}

// ---------------- L1b: reduce partials -> c = mean / sqrt(var_ddof1 + 1e-4) ----------------
__global__ void colstats_red_k() {
    int idx = blockIdx.x * 256 + threadIdx.x;          // 0..2047
    int isY = idx >> 10, col = idx & (DD - 1);
    double s = 0.0, s2 = 0.0;
#pragma unroll
    for (int z = 0; z < ZCH; z++) { s += g_cps[isY][z][col]; s2 += g_cps2[isY][z][col]; }
    double mean = s / (double)NN;
    double var  = (s2 - (double)NN * mean * mean) / (double)(NN - 1);
    float  c    = (float)(mean / sqrt(var + 1e-4));
    (isY ? g_cy : g_cx)[col] = c;
}

// ---------------- L2: fused normalize + row squared norm ----------------
__global__ void normrow_k(const float* __restrict__ X, const float* __restrict__ Y) {
    int isY = blockIdx.y;
    const float* A = isY ? Y : X;
    const float* C = isY ? g_cy : g_cx;
    float* O       = isY ? g_Yn : g_Xn;
    int r = blockIdx.x, t = threadIdx.x;             // 256 threads
    float4 a = ((const float4*)(A + (size_t)r * DD))[t];
    float4 c = ((const float4*)C)[t];
    float4 o = make_float4(a.x - c.x, a.y - c.y, a.z - c.z, a.w - c.w);
    ((float4*)(O + (size_t)r * DD))[t] = o;
    double s = (double)o.x * o.x + (double)o.y * o.y + (double)o.z * o.z + (double)o.w * o.w;
    __shared__ double sh[256];
    sh[t] = s; __syncthreads();
    for (int off = 128; off > 0; off >>= 1) {
        if (t < off) sh[t] += sh[t + off];
        __syncthreads();
    }
    if (t == 0) (isY ? g_ysq : g_xsq)[r] = (float)sh[0];
}

// ---------------- L3: band GEMM (split-K x8) + fused d/la/kappa epilogue ----------------
__global__ void band_gemm_k() {
    int ti = blockIdx.x;
    int i0 = ti * 32;
    int j0 = i0 - 32;
    int cz = blockIdx.y;

    __shared__ float Xs[32][33];
    __shared__ float Ys[96][33];
    int tid = threadIdx.x;                           // 256 threads
    int tx = tid & 31, ty = tid >> 5;
    float acc[4][3];
#pragma unroll
    for (int a = 0; a < 4; a++)
#pragma unroll
        for (int bb = 0; bb < 3; bb++) acc[a][bb] = 0.f;

    for (int k0 = 0; k0 < KLEN; k0 += 32) {
        {
            int r = tid >> 3, q = tid & 7;
            float4 v = *(const float4*)(g_Xn + (size_t)(i0 + r) * DD + cz * KLEN + k0 + q * 4);
            Xs[r][q * 4 + 0] = v.x; Xs[r][q * 4 + 1] = v.y;
            Xs[r][q * 4 + 2] = v.z; Xs[r][q * 4 + 3] = v.w;
        }
#pragma unroll
        for (int l = 0; l < 3; l++) {
            int li = tid + l * 256;
            int r = li >> 3, q = li & 7;
            int gj = j0 + r;
            float4 v = make_float4(0.f, 0.f, 0.f, 0.f);
            if ((unsigned)gj < NN)
                v = *(const float4*)(g_Yn + (size_t)gj * DD + cz * KLEN + k0 + q * 4);
            Ys[r][q * 4 + 0] = v.x; Ys[r][q * 4 + 1] = v.y;
            Ys[r][q * 4 + 2] = v.z; Ys[r][q * 4 + 3] = v.w;
        }
        __syncthreads();
#pragma unroll
        for (int kk = 0; kk < 32; kk++) {
            float av[4], bv[3];
#pragma unroll
            for (int a = 0; a < 4; a++) av[a] = Xs[ty * 4 + a][kk];
#pragma unroll
            for (int bb = 0; bb < 3; bb++) bv[bb] = Ys[tx * 3 + bb][kk];
#pragma unroll
            for (int a = 0; a < 4; a++)
#pragma unroll
                for (int bb = 0; bb < 3; bb++) acc[a][bb] += av[a] * bv[bb];
        }
        __syncthreads();
    }

#pragma unroll
    for (int a = 0; a < 4; a++) {
        int gi = i0 + ty * 4 + a;
#pragma unroll
        for (int bb = 0; bb < 3; bb++) {
            int gj = j0 + tx * 3 + bb;
            int c = gj - gi + BAND;
            if ((unsigned)gj < NN && c >= 0 && c < WB)
                g_dpart[((size_t)cz * NN + gi) * WB + c] = acc[a][bb];
        }
    }

    // split-K fixup: last arriver runs the epilogue (deterministic math)
    __shared__ int s_old;
    __shared__ double sla[32];
    __threadfence();
    __syncthreads();
    if (tid == 0) s_old = atomicAdd(&g_tilecnt[ti], 1);
    __syncthreads();
    if (s_old != KCH - 1) return;
    __threadfence();

    for (int idx = tid; idx < 32 * WB; idx += 256) {
        int rl = idx / WB, c = idx - rl * WB;
        int r = i0 + rl, p = r + c - BAND;
        float d = 0.f;
        if ((unsigned)p < NN) {
            float dot = 0.f;
#pragma unroll
            for (int z = 0; z < KCH; z++)
                dot += __ldcg(&g_dpart[(size_t)(z * NN + r) * WB + c]);
            d = g_xsq[r] + g_ysq[p] - 2.0f * dot;
        }
        g_dband[(size_t)r * WB + c] = d;
        if (c == BAND) {
            double la = g_lps[BAND] - (double)d * K2;
            g_la[r] = la;
            sla[rl] = la;
        }
    }
    __syncthreads();
    for (int idx = tid; idx < 32 * WB; idx += 256) {
        int rl = idx / WB, c = idx - rl * WB;
        int r = i0 + rl, p = r + c - BAND;
        float val = 0.f;
        if ((unsigned)p < NN) {
            double arg = g_lps[c] - (double)g_dband[(size_t)r * WB + c] * K2 - sla[rl];
            val = exp2f((float)arg);
        }
        g_kbR[(size_t)r * WB + c] = val;
        g_kbC[(size_t)c * NN + r] = val;
        if ((unsigned)p < NN) g_kbTC[(size_t)(2 * BAND - c) * NN + p] = val;
        else                  g_kbTC[(size_t)c * NN + r] = 0.f;
    }
}

// ---------------- reg-kappa banded dot (kr in registers, uw in smem) ----------------
__device__ __forceinline__ float rdot49(const float* kr, const float* __restrict__ uw) {
    float a0 = 0.f, a1 = 0.f, a2 = 0.f, a3 = 0.f;
#pragma unroll
    for (int c = 0; c < 48; c += 4) {
        a0 = fmaf(kr[c + 0], uw[c + 0], a0);
        a1 = fmaf(kr[c + 1], uw[c + 1], a1);
        a2 = fmaf(kr[c + 2], uw[c + 2], a2);
        a3 = fmaf(kr[c + 3], uw[c + 3], a3);
    }
    a0 = fmaf(kr[48], uw[48], a0);
    return (a0 + a1) + (a2 + a3);
}

// ---------------- L4: cluster Sinkhorn — kappa in registers, 1 thread per dot-row ----------
// v-threads: tid<96 boundary (t = tid<48 ? tid : 208+tid), tid 96..303 interior (t=tid-48).
// u-threads: tid 320..575 own rows (r = tid-320). Warps 0-2 = boundary v (bar.sync 1,96).
__global__ void __launch_bounds__(STPB, 1) __cluster_dims__(NCL, 1, 1)
sink_k() {
    const int tid = threadIdx.x;
    const int rk = (int)ctarank();
    const int R0 = rk * RPC;
    __shared__ float su[2][WIN];    // u rows [R0-48, R0+304), double-buffered
    __shared__ float sv[EXT];       // v rows [R0-24, R0+280)
    __shared__ float sw[EXT];
    __shared__ double sred[256];
    __shared__ unsigned long long mbar_s;
    const uint32_t mb = smem_u32(&mbar_s);

    int vt = -1;
    if (tid < 96)        vt = (tid < 48) ? tid : 208 + tid;
    else if (tid < 304)  vt = tid - 48;
    const int ur = (tid >= 320 && tid < 576) ? tid - 320 : -1;
    const int vj = (vt >= 0) ? (R0 - 24 + vt) : -1;
    const int vvalid = (vt >= 0) && ((unsigned)vj < NN);

    float ka[WB];                   // own kappa row, iteration-invariant
    if (vt >= 0) {
#pragma unroll
        for (int c = 0; c < WB; c++)
            ka[c] = vvalid ? __ldcg(&g_kbTC[(size_t)c * NN + vj]) : 0.f;
    } else if (ur >= 0) {
#pragma unroll
        for (int c = 0; c < WB; c++)
            ka[c] = __ldcg(&g_kbC[(size_t)c * NN + R0 + ur]);
    }

    if (tid == 0) {
        int expect = (rk > 0 ? 48 : 0) + (rk < NCL - 1 ? 48 : 0);
        MBAR_INIT(mb, expect);
    }
    for (int q = tid; q < 2 * WIN; q += STPB) ((float*)su)[q] = 0.f;
    double la0 = g_la[0];
    double myla = (ur >= 0) ? g_la[R0 + ur] : 0.0;
    __syncthreads();
    CLUSTER_SYNC();                 // barrier + zeroed windows visible cluster-wide

    int ev = 0;

    auto PUBLISH = [&](int nb, float val) {    // u-threads only
        su[nb][48 + ur] = val;
        if (rk > 0 && ur < 48)
            PUSH_ARRIVE(smem_u32(&su[nb][304 + ur]), mb, rk - 1, val);
        if (rk < NCL - 1 && ur >= 208)
            PUSH_ARRIVE(smem_u32(&su[nb][ur - 208]), mb, rk + 1, val);
    };
    auto FUSED = [&]() {
        const float* ub = su[ev & 1];
        if (vt >= 0) {
            if (tid < 96) {                    // boundary: wait for halo first
                if (tid == 0) TRYWAIT_PAR(mb, ev & 1);
                BARSYNC96();
            }
            float s = rdot49(ka, ub + vt);
            sv[vt] = vvalid ? INV_M / s : 0.f;
        }
        __syncthreads();
        int nb = (ev + 1) & 1;
        if (ur >= 0) {
            float un = 1.0f / ((float)NN * rdot49(ka, sv + ur));
            PUBLISH(nb, un);
        }
        ev++;
        __syncthreads();
    };

    // event 0: u0 = a_i/a_0 (lambda-rescaled init; iteration is lambda-invariant)
    if (ur >= 0) PUBLISH(0, exp2f((float)(myla - la0)));
    __syncthreads();
    FUSED();                        // u1 (ev=1)
    FUSED();                        // v2 in sv, u2 (ev=2)

    // crit: w = kT u2 over ext rows (sv preserved)
    {
        const float* ub = su[ev & 1];
        if (vt >= 0) {
            if (tid < 96) {
                if (tid == 0) TRYWAIT_PAR(mb, ev & 1);
                BARSYNC96();
            }
            float s = rdot49(ka, ub + vt);
            sw[vt] = vvalid ? s : 0.f;
        }
    }
    __syncthreads();
    if (tid < 256)
        sred[tid] = fabs((double)sv[tid + 24] * (double)sw[tid + 24] - 1.0 / (double)MM);
    __syncthreads();
    for (int o = 128; o; o >>= 1) {
        if (tid < o) sred[tid] += sred[tid + o];
        __syncthreads();
    }
    if (tid == 0) g_part[rk] = sred[0];
    __threadfence();
    CLUSTER_SYNC();
    double crit = 0.0;
    for (int q = 0; q < NCL; q++) crit += __ldcg(&g_part[q]);
    int done = ((crit < 0.005) || (crit != crit)) ? 1 : 0;

    if (!done) {
        // plain update 1: v3 = b/w (local), u3 (ev=3)
        if (vt >= 0) sv[vt] = vvalid ? INV_M / sw[vt] : 0.f;
        __syncthreads();
        int nb = (ev + 1) & 1;
        if (ur >= 0) {
            float un = 1.0f / ((float)NN * rdot49(ka, sv + ur));
            PUBLISH(nb, un);
        }
        ev++;
        __syncthreads();
        for (int it = 0; it < 18; it++) FUSED();   // 17 plain + final special; ev = 21
    }

    CLUSTER_SYNC();                 // all inbound pushes landed; safe to export+exit
    if (tid < 256) {
        g_u[R0 + tid] = su[ev & 1][48 + tid];
        g_v[R0 + tid] = sv[tid + 24];
    }
}

// ---------------- L5: full-chip finalize: t rows + dis (last-arriver) ----------------
__global__ void finalize_k(float* __restrict__ tbase, float* __restrict__ disp) {
    int bid = blockIdx.x, tid = threadIdx.x;          // 256 blocks x 256 threads
    double dp = 0.0;
    for (int rl = 0; rl < 8; rl++) {
        int i = bid * 8 + rl;
        float ui = g_u[i];
        const float* kr = g_kbR + (size_t)i * WB;
        const float* dr = g_dband + (size_t)i * WB;
        if (tbase) {
            float* orow = tbase + (size_t)i * MM;
            for (int j = tid; j < MM; j += 256) {
                int c = j - i + BAND;
                float tv = 0.f;
                if ((unsigned)c < WB) {
                    tv = ui * __ldg(&kr[c]) * g_v[j];
                    dp += (double)tv * (double)__ldg(&dr[c]);
                }
                orow[j] = tv;
            }
        } else {
            for (int j = tid; j < MM; j += 256) {
                int c = j - i + BAND;
                if ((unsigned)c < WB)
                    dp += (double)(ui * __ldg(&kr[c]) * g_v[j]) * (double)__ldg(&dr[c]);
            }
        }
    }
    __shared__ double sh[256];
    __shared__ int s_last;
    sh[tid] = dp; __syncthreads();
    for (int o = 128; o; o >>= 1) { if (tid < o) sh[tid] += sh[tid + o]; __syncthreads(); }
    if (tid == 0) g_part2[bid] = sh[0];
    __threadfence();
    __syncthreads();
    if (tid == 0) s_last = atomicAdd(&g_fincnt, 1);
    __syncthreads();
    if (s_last != 255) return;
    __threadfence();
    sh[tid] = __ldcg(&g_part2[tid]);
    __syncthreads();
    for (int o = 128; o; o >>= 1) { if (tid < o) sh[tid] += sh[tid + o]; __syncthreads(); }
    if (tid == 0 && disp) disp[0] = (float)sh[0];
}

// ---------------- host ----------------
extern "C" void kernel_launch(void* const* d_in, const int* in_sizes, int n_in,
                              void* d_out, int out_size) {
    (void)in_sizes; (void)n_in;
    const float* X = (const float*)d_in[0];
    const float* Y = (const float*)d_in[1];

    colstats_part_k<<<dim3(DD / 32, 2, ZCH), dim3(32, 8)>>>(X, Y);
    colstats_red_k <<<(2 * DD) / 256, 256>>>();
    normrow_k      <<<dim3(NN, 2), 256>>>(X, Y);
    band_gemm_k    <<<dim3(NTILE, KCH), 256>>>();
    sink_k         <<<NCL, STPB>>>();

    float* out = (float*)d_out;
    long long total = (long long)NN * (long long)MM;
    float* tbase = 0;
    float* disp  = 0;
    if ((long long)out_size == total + 1) { disp = out; tbase = out + 1; }
    else if ((long long)out_size >= total) { tbase = out; }
    else { disp = out; }

    finalize_k<<<256, 256>>>(tbase, disp);
}